// round 1
// baseline (speedup 1.0000x reference)
#include <cuda_runtime.h>
#include <cstdint>
#include <cstddef>

#define TTOK   8192
#define DMODEL 1024
#define FDIM   4096
#define NEXP   8

// ---------------- scratch (static device memory; no allocations) ------------
__device__ int   g_cnt[NEXP];
__device__ int   g_list[NEXP][TTOK];            // value = token*2 + k_slot
__device__ float g_wslot[2 * TTOK];             // renormalized top-2 weights per slot
__device__ float g_H[(size_t)2 * TTOK * FDIM];  // per-slot hidden (256 MB)
__device__ float g_O[(size_t)2 * TTOK * DMODEL];// per-slot expert output (64 MB)

__global__ void k_init() {
    if (threadIdx.x < NEXP) g_cnt[threadIdx.x] = 0;
}

// ---------------- router: logits, top-2, expert lists ----------------------
__global__ void __launch_bounds__(256) k_router(const float* __restrict__ x,
                                                const float* __restrict__ gw,
                                                float* logits) {
    __shared__ float sgw[NEXP * DMODEL];
    const int tid = threadIdx.x;
    for (int i = tid; i < NEXP * DMODEL / 4; i += 256)
        ((float4*)sgw)[i] = ((const float4*)gw)[i];
    __syncthreads();

    const int warp = tid >> 5, lane = tid & 31;
    const int t = blockIdx.x * 8 + warp;

    float acc[NEXP];
    #pragma unroll
    for (int e = 0; e < NEXP; e++) acc[e] = 0.f;

    const float4* xv = (const float4*)(x + (size_t)t * DMODEL);
    #pragma unroll
    for (int c = 0; c < DMODEL / 128; c++) {
        float4 xx = xv[c * 32 + lane];
        #pragma unroll
        for (int e = 0; e < NEXP; e++) {
            float4 g = ((const float4*)sgw)[e * (DMODEL / 4) + c * 32 + lane];
            acc[e] += xx.x * g.x + xx.y * g.y + xx.z * g.z + xx.w * g.w;
        }
    }
    #pragma unroll
    for (int off = 16; off > 0; off >>= 1) {
        #pragma unroll
        for (int e = 0; e < NEXP; e++)
            acc[e] += __shfl_xor_sync(0xffffffffu, acc[e], off);
    }

    if (lane == 0) {
        if (logits) {
            #pragma unroll
            for (int e = 0; e < NEXP; e++) logits[(size_t)t * NEXP + e] = acc[e];
        }
        int e0 = 0;
        #pragma unroll
        for (int e = 1; e < NEXP; e++) if (acc[e] > acc[e0]) e0 = e;
        int e1 = -1;
        #pragma unroll
        for (int e = 0; e < NEXP; e++) {
            if (e == e0) continue;
            if (e1 < 0 || acc[e] > acc[e1]) e1 = e;
        }
        // renormalized top-2 softmax weights: w0 = sigmoid(l0 - l1)
        float w0 = 1.f / (1.f + expf(acc[e1] - acc[e0]));
        float w1 = 1.f - w0;
        int s0 = atomicAdd(&g_cnt[e0], 1);
        g_list[e0][s0] = t * 2;
        int s1 = atomicAdd(&g_cnt[e1], 1);
        g_list[e1][s1] = t * 2 + 1;
        g_wslot[2 * t]     = w0;
        g_wslot[2 * t + 1] = w1;
    }
}

// ---------------- GEMM1: H = silu(x@W1) * (x@W3), gathered rows ------------
// tile: 128 (tokens) x 64 (F cols) x 16 (K), 256 threads, thread tile 8x4 x2 mats
__global__ void __launch_bounds__(256) k_gemm1(const float* __restrict__ x,
                                               const float* __restrict__ W1,
                                               const float* __restrict__ W3) {
    const int e   = blockIdx.z;
    const int cnt = g_cnt[e];
    const int m0  = blockIdx.y * 128;
    if (m0 >= cnt) return;
    const int n0  = blockIdx.x * 64;

    __shared__ float As[16][128];
    __shared__ float B1s[16][64];
    __shared__ float B3s[16][64];
    __shared__ int   sv[128];

    const int tid = threadIdx.x;
    if (tid < 128) {
        int m = m0 + tid;
        sv[tid] = (m < cnt) ? g_list[e][m] : -1;
    }
    __syncthreads();

    const int ar = tid >> 1;
    const int ak = (tid & 1) << 3;
    const int svr = sv[ar];
    const bool avalid = (svr >= 0);
    const float* aptr = x + (size_t)(avalid ? (svr >> 1) : 0) * DMODEL + ak;

    const int br = tid >> 4;            // 0..15
    const int bc = (tid & 15) << 2;     // 0..60
    const float* b1p = W1 + ((size_t)e * DMODEL + br) * FDIM + n0 + bc;
    const float* b3p = W3 + ((size_t)e * DMODEL + br) * FDIM + n0 + bc;

    const int tx = tid & 15;
    const int ty = tid >> 4;

    float acc1[8][4], acc3[8][4];
    #pragma unroll
    for (int i = 0; i < 8; i++)
        #pragma unroll
        for (int j = 0; j < 4; j++) { acc1[i][j] = 0.f; acc3[i][j] = 0.f; }

    const float4 z4 = make_float4(0.f, 0.f, 0.f, 0.f);
    float4 ra0 = avalid ? *(const float4*)(aptr)     : z4;
    float4 ra1 = avalid ? *(const float4*)(aptr + 4) : z4;
    float4 rb1 = *(const float4*)(b1p);
    float4 rb3 = *(const float4*)(b3p);

    const int NK = DMODEL / 16;
    for (int kt = 0; kt < NK; ++kt) {
        As[ak + 0][ar] = ra0.x; As[ak + 1][ar] = ra0.y;
        As[ak + 2][ar] = ra0.z; As[ak + 3][ar] = ra0.w;
        As[ak + 4][ar] = ra1.x; As[ak + 5][ar] = ra1.y;
        As[ak + 6][ar] = ra1.z; As[ak + 7][ar] = ra1.w;
        *(float4*)&B1s[br][bc] = rb1;
        *(float4*)&B3s[br][bc] = rb3;
        __syncthreads();
        if (kt + 1 < NK) {
            const int ko = (kt + 1) * 16;
            ra0 = avalid ? *(const float4*)(aptr + ko)     : z4;
            ra1 = avalid ? *(const float4*)(aptr + ko + 4) : z4;
            rb1 = *(const float4*)(b1p + (size_t)ko * FDIM);
            rb3 = *(const float4*)(b3p + (size_t)ko * FDIM);
        }
        #pragma unroll
        for (int kk = 0; kk < 16; ++kk) {
            float a[8];
            *(float4*)&a[0] = *(const float4*)&As[kk][ty * 8];
            *(float4*)&a[4] = *(const float4*)&As[kk][ty * 8 + 4];
            float4 b1 = *(const float4*)&B1s[kk][tx * 4];
            float4 b3 = *(const float4*)&B3s[kk][tx * 4];
            #pragma unroll
            for (int i = 0; i < 8; i++) {
                acc1[i][0] += a[i] * b1.x; acc1[i][1] += a[i] * b1.y;
                acc1[i][2] += a[i] * b1.z; acc1[i][3] += a[i] * b1.w;
                acc3[i][0] += a[i] * b3.x; acc3[i][1] += a[i] * b3.y;
                acc3[i][2] += a[i] * b3.z; acc3[i][3] += a[i] * b3.w;
            }
        }
        __syncthreads();
    }

    #pragma unroll
    for (int i = 0; i < 8; i++) {
        const int v = sv[ty * 8 + i];
        if (v < 0) continue;
        float4 h;
        h.x = acc1[i][0] / (1.f + expf(-acc1[i][0])) * acc3[i][0];
        h.y = acc1[i][1] / (1.f + expf(-acc1[i][1])) * acc3[i][1];
        h.z = acc1[i][2] / (1.f + expf(-acc1[i][2])) * acc3[i][2];
        h.w = acc1[i][3] / (1.f + expf(-acc1[i][3])) * acc3[i][3];
        *(float4*)(g_H + (size_t)v * FDIM + n0 + tx * 4) = h;
    }
}

// ---------------- GEMM2: O = H @ W2 (per-expert, gathered rows) -------------
// tile: 128 x 128 x (K=8), 256 threads, thread tile 8x8 (split 2x 4-col groups)
__global__ void __launch_bounds__(256) k_gemm2(const float* __restrict__ W2) {
    const int e   = blockIdx.z;
    const int cnt = g_cnt[e];
    const int m0  = blockIdx.y * 128;
    if (m0 >= cnt) return;
    const int n0  = blockIdx.x * 128;

    __shared__ float As[8][128];
    __shared__ float Bs[8][128];
    __shared__ int   sv[128];

    const int tid = threadIdx.x;
    if (tid < 128) {
        int m = m0 + tid;
        sv[tid] = (m < cnt) ? g_list[e][m] : -1;
    }
    __syncthreads();

    const int ar = tid >> 1;
    const int ak = (tid & 1) << 2;
    const int svr = sv[ar];
    const bool avalid = (svr >= 0);
    const float* aptr = g_H + (size_t)(avalid ? svr : 0) * FDIM + ak;

    const int br = tid >> 5;            // 0..7
    const int bc = (tid & 31) << 2;     // 0..124
    const float* bp = W2 + ((size_t)e * FDIM + br) * DMODEL + n0 + bc;

    const int tx = tid & 15;
    const int ty = tid >> 4;

    float acc[8][8];
    #pragma unroll
    for (int i = 0; i < 8; i++)
        #pragma unroll
        for (int j = 0; j < 8; j++) acc[i][j] = 0.f;

    const float4 z4 = make_float4(0.f, 0.f, 0.f, 0.f);
    float4 ra = avalid ? *(const float4*)aptr : z4;
    float4 rb = *(const float4*)bp;

    const int NK = FDIM / 8;  // 512
    for (int kt = 0; kt < NK; ++kt) {
        As[ak + 0][ar] = ra.x; As[ak + 1][ar] = ra.y;
        As[ak + 2][ar] = ra.z; As[ak + 3][ar] = ra.w;
        *(float4*)&Bs[br][bc] = rb;
        __syncthreads();
        if (kt + 1 < NK) {
            ra = avalid ? *(const float4*)(aptr + (size_t)(kt + 1) * 8) : z4;
            rb = *(const float4*)(bp + (size_t)(kt + 1) * 8 * DMODEL);
        }
        #pragma unroll
        for (int kk = 0; kk < 8; ++kk) {
            float a[8], b[8];
            *(float4*)&a[0] = *(const float4*)&As[kk][ty * 8];
            *(float4*)&a[4] = *(const float4*)&As[kk][ty * 8 + 4];
            *(float4*)&b[0] = *(const float4*)&Bs[kk][tx * 4];
            *(float4*)&b[4] = *(const float4*)&Bs[kk][64 + tx * 4];
            #pragma unroll
            for (int i = 0; i < 8; i++)
                #pragma unroll
                for (int j = 0; j < 8; j++)
                    acc[i][j] += a[i] * b[j];
        }
        __syncthreads();
    }

    #pragma unroll
    for (int i = 0; i < 8; i++) {
        const int v = sv[ty * 8 + i];
        if (v < 0) continue;
        float* op = g_O + (size_t)v * DMODEL + n0;
        *(float4*)(op + tx * 4)      = make_float4(acc[i][0], acc[i][1], acc[i][2], acc[i][3]);
        *(float4*)(op + 64 + tx * 4) = make_float4(acc[i][4], acc[i][5], acc[i][6], acc[i][7]);
    }
}

// ---------------- combine: out[t] = w0*O[2t] + w1*O[2t+1] -------------------
__global__ void k_combine(float* __restrict__ out) {
    const int i  = blockIdx.x * blockDim.x + threadIdx.x;  // float4 index
    const int n4 = TTOK * DMODEL / 4;
    if (i >= n4) return;
    const int t = i / (DMODEL / 4);
    const int c = i % (DMODEL / 4);
    const float w0 = g_wslot[2 * t], w1 = g_wslot[2 * t + 1];
    const float4 o0 = ((const float4*)g_O)[(size_t)(2 * t)     * (DMODEL / 4) + c];
    const float4 o1 = ((const float4*)g_O)[(size_t)(2 * t + 1) * (DMODEL / 4) + c];
    float4 r;
    r.x = w0 * o0.x + w1 * o1.x;
    r.y = w0 * o0.y + w1 * o1.y;
    r.z = w0 * o0.z + w1 * o1.z;
    r.w = w0 * o0.w + w1 * o1.w;
    ((float4*)out)[i] = r;
}

// ---------------- launch -----------------------------------------------------
extern "C" void kernel_launch(void* const* d_in, const int* in_sizes, int n_in,
                              void* d_out, int out_size) {
    const float* x  = (const float*)d_in[0];
    const float* gw = (const float*)d_in[1];
    const float* W1 = (const float*)d_in[2];
    const float* W3 = (const float*)d_in[3];
    const float* W2 = (const float*)d_in[4];
    float* out = (float*)d_out;

    // assumed packing: [out (T*D floats)] [router_logits (T*E floats)]
    float* logits = ((size_t)out_size >= (size_t)TTOK * DMODEL + (size_t)TTOK * NEXP)
                        ? out + (size_t)TTOK * DMODEL
                        : nullptr;

    k_init<<<1, 32>>>();
    k_router<<<TTOK / 8, 256>>>(x, gw, logits);
    k_gemm1<<<dim3(FDIM / 64, TTOK / 128, NEXP), 256>>>(x, W1, W3);
    k_gemm2<<<dim3(DMODEL / 128, TTOK / 128, NEXP), 256>>>(W2);
    k_combine<<<(TTOK * DMODEL / 4 + 255) / 256, 256>>>(out);
}

// round 2
// speedup vs baseline: 2.2558x; 2.2558x over previous
#include <cuda_runtime.h>
#include <cstdint>
#include <cstddef>

#define TTOK   8192
#define DMODEL 1024
#define FDIM   4096
#define NEXP   8

// ---------------- scratch (static device memory; no allocations) ------------
__device__ int   g_cnt[NEXP];
__device__ int   g_list[NEXP][TTOK];            // value = token*2 + k_slot
__device__ float g_wslot[2 * TTOK];             // renormalized top-2 weights per slot
__device__ float g_H[(size_t)2 * TTOK * FDIM];  // per-slot hidden (256 MB)
__device__ float g_O[(size_t)2 * TTOK * DMODEL];// per-slot expert output (64 MB)

__global__ void k_init() {
    if (threadIdx.x < NEXP) g_cnt[threadIdx.x] = 0;
}

// ---------------- helpers ----------------------------------------------------
__device__ __forceinline__ float tf32r(float f) {
    uint32_t u;
    asm("cvt.rna.tf32.f32 %0, %1;" : "=r"(u) : "f"(f));
    return __uint_as_float(u);
}

#define MMA_TF32(C, A, B0, B1)                                               \
    asm volatile(                                                            \
        "mma.sync.aligned.m16n8k8.row.col.f32.tf32.tf32.f32 "               \
        "{%0,%1,%2,%3},{%4,%5,%6,%7},{%8,%9},{%0,%1,%2,%3};"                \
        : "+f"((C)[0]), "+f"((C)[1]), "+f"((C)[2]), "+f"((C)[3])            \
        : "r"((A)[0]), "r"((A)[1]), "r"((A)[2]), "r"((A)[3]),               \
          "r"(B0), "r"(B1))

// ---------------- router: logits, top-2, expert lists ----------------------
__global__ void __launch_bounds__(256) k_router(const float* __restrict__ x,
                                                const float* __restrict__ gw,
                                                float* logits) {
    __shared__ float sgw[NEXP * DMODEL];
    const int tid = threadIdx.x;
    for (int i = tid; i < NEXP * DMODEL / 4; i += 256)
        ((float4*)sgw)[i] = ((const float4*)gw)[i];
    __syncthreads();

    const int warp = tid >> 5, lane = tid & 31;
    const int t = blockIdx.x * 8 + warp;

    float acc[NEXP];
    #pragma unroll
    for (int e = 0; e < NEXP; e++) acc[e] = 0.f;

    const float4* xv = (const float4*)(x + (size_t)t * DMODEL);
    #pragma unroll
    for (int c = 0; c < DMODEL / 128; c++) {
        float4 xx = xv[c * 32 + lane];
        #pragma unroll
        for (int e = 0; e < NEXP; e++) {
            float4 g = ((const float4*)sgw)[e * (DMODEL / 4) + c * 32 + lane];
            acc[e] += xx.x * g.x + xx.y * g.y + xx.z * g.z + xx.w * g.w;
        }
    }
    #pragma unroll
    for (int off = 16; off > 0; off >>= 1) {
        #pragma unroll
        for (int e = 0; e < NEXP; e++)
            acc[e] += __shfl_xor_sync(0xffffffffu, acc[e], off);
    }

    if (lane == 0) {
        if (logits) {
            #pragma unroll
            for (int e = 0; e < NEXP; e++) logits[(size_t)t * NEXP + e] = acc[e];
        }
        int e0 = 0;
        #pragma unroll
        for (int e = 1; e < NEXP; e++) if (acc[e] > acc[e0]) e0 = e;
        int e1 = -1;
        #pragma unroll
        for (int e = 0; e < NEXP; e++) {
            if (e == e0) continue;
            if (e1 < 0 || acc[e] > acc[e1]) e1 = e;
        }
        float w0 = 1.f / (1.f + expf(acc[e1] - acc[e0]));
        float w1 = 1.f - w0;
        int s0 = atomicAdd(&g_cnt[e0], 1);
        g_list[e0][s0] = t * 2;
        int s1 = atomicAdd(&g_cnt[e1], 1);
        g_list[e1][s1] = t * 2 + 1;
        g_wslot[2 * t]     = w0;
        g_wslot[2 * t + 1] = w1;
    }
}

// ---------------- GEMM1 (tensor core): H = silu(x@W1) * (x@W3) --------------
// BM=128, BN=64 per matrix (both W1,W3), BK=32. 8 warps = 4(m) x 2(n).
// Warp tile 32x32 per matrix: 2 m-tiles(16) x 4 n-tiles(8), mma m16n8k8 tf32.
__global__ void __launch_bounds__(256) k_gemm1(const float* __restrict__ x,
                                               const float* __restrict__ W1,
                                               const float* __restrict__ W3) {
    const int e   = blockIdx.z;
    const int cnt = g_cnt[e];
    const int m0  = blockIdx.x * 128;
    if (m0 >= cnt) return;
    const int n0  = blockIdx.y * 64;

    __shared__ float As[128][36];     // row-major, padded
    __shared__ float B1s[32][72];     // [k][n], padded: bank = 8k+n (bijective)
    __shared__ float B3s[32][72];
    __shared__ int   sv[128];

    const int tid = threadIdx.x;
    if (tid < 128) {
        int m = m0 + tid;
        sv[tid] = (m < cnt) ? g_list[e][m] : -1;
    }
    __syncthreads();

    // A producer: thread -> row ar, 16 consecutive k at offset ak
    const int ar = tid >> 1, ak = (tid & 1) * 16;
    const int svr = sv[ar];
    const float* aptr = x + (size_t)((svr < 0 ? 0 : svr) >> 1) * DMODEL + ak;

    // B producer: thread -> k-row kr, 8 cols at nc
    const int kr = tid >> 3, nc = (tid & 7) * 8;
    const float* b1p = W1 + ((size_t)e * DMODEL + kr) * FDIM + n0 + nc;
    const float* b3p = W3 + ((size_t)e * DMODEL + kr) * FDIM + n0 + nc;

    const int wid = tid >> 5, lane = tid & 31;
    const int wm = wid & 3, wn = wid >> 2;
    const int fr = lane >> 2, fc = lane & 3;

    float acc1[2][4][4], acc3[2][4][4];
    #pragma unroll
    for (int i = 0; i < 2; i++)
        #pragma unroll
        for (int n = 0; n < 4; n++)
            #pragma unroll
            for (int q = 0; q < 4; q++) { acc1[i][n][q] = 0.f; acc3[i][n][q] = 0.f; }

    float4 pa[4], pb1[2], pb3[2];
    #pragma unroll
    for (int j = 0; j < 4; j++) pa[j] = *(const float4*)(aptr + 4 * j);
    pb1[0] = *(const float4*)(b1p);     pb1[1] = *(const float4*)(b1p + 4);
    pb3[0] = *(const float4*)(b3p);     pb3[1] = *(const float4*)(b3p + 4);

    const int NK = DMODEL / 32;
    for (int kt = 0; kt < NK; ++kt) {
        #pragma unroll
        for (int j = 0; j < 4; j++) {
            float4 c;
            c.x = tf32r(pa[j].x); c.y = tf32r(pa[j].y);
            c.z = tf32r(pa[j].z); c.w = tf32r(pa[j].w);
            *(float4*)&As[ar][ak + 4 * j] = c;
        }
        {
            float4 c;
            c.x = tf32r(pb1[0].x); c.y = tf32r(pb1[0].y); c.z = tf32r(pb1[0].z); c.w = tf32r(pb1[0].w);
            *(float4*)&B1s[kr][nc] = c;
            c.x = tf32r(pb1[1].x); c.y = tf32r(pb1[1].y); c.z = tf32r(pb1[1].z); c.w = tf32r(pb1[1].w);
            *(float4*)&B1s[kr][nc + 4] = c;
            c.x = tf32r(pb3[0].x); c.y = tf32r(pb3[0].y); c.z = tf32r(pb3[0].z); c.w = tf32r(pb3[0].w);
            *(float4*)&B3s[kr][nc] = c;
            c.x = tf32r(pb3[1].x); c.y = tf32r(pb3[1].y); c.z = tf32r(pb3[1].z); c.w = tf32r(pb3[1].w);
            *(float4*)&B3s[kr][nc + 4] = c;
        }
        __syncthreads();
        if (kt + 1 < NK) {
            const int ko = (kt + 1) * 32;
            #pragma unroll
            for (int j = 0; j < 4; j++) pa[j] = *(const float4*)(aptr + ko + 4 * j);
            pb1[0] = *(const float4*)(b1p + (size_t)ko * FDIM);
            pb1[1] = *(const float4*)(b1p + (size_t)ko * FDIM + 4);
            pb3[0] = *(const float4*)(b3p + (size_t)ko * FDIM);
            pb3[1] = *(const float4*)(b3p + (size_t)ko * FDIM + 4);
        }
        #pragma unroll
        for (int s = 0; s < 4; s++) {
            const int kb = s * 8;
            uint32_t a[2][4];
            #pragma unroll
            for (int i = 0; i < 2; i++) {
                const int r = wm * 32 + i * 16 + fr;
                a[i][0] = __float_as_uint(As[r][kb + fc]);
                a[i][1] = __float_as_uint(As[r + 8][kb + fc]);
                a[i][2] = __float_as_uint(As[r][kb + fc + 4]);
                a[i][3] = __float_as_uint(As[r + 8][kb + fc + 4]);
            }
            #pragma unroll
            for (int n = 0; n < 4; n++) {
                const int nb = wn * 32 + n * 8 + fr;
                uint32_t b10 = __float_as_uint(B1s[kb + fc][nb]);
                uint32_t b11 = __float_as_uint(B1s[kb + fc + 4][nb]);
                uint32_t b30 = __float_as_uint(B3s[kb + fc][nb]);
                uint32_t b31 = __float_as_uint(B3s[kb + fc + 4][nb]);
                #pragma unroll
                for (int i = 0; i < 2; i++) {
                    MMA_TF32(acc1[i][n], a[i], b10, b11);
                    MMA_TF32(acc3[i][n], a[i], b30, b31);
                }
            }
        }
        __syncthreads();
    }

    // epilogue: silu(acc1)*acc3 -> g_H
    #pragma unroll
    for (int i = 0; i < 2; i++) {
        const int r0 = wm * 32 + i * 16 + fr;
        const int r1 = r0 + 8;
        const int v0 = sv[r0], v1 = sv[r1];
        #pragma unroll
        for (int n = 0; n < 4; n++) {
            const int col = n0 + wn * 32 + n * 8 + fc * 2;
            if (v0 >= 0) {
                float g0 = acc1[i][n][0], g1 = acc1[i][n][1];
                float2 h;
                h.x = g0 / (1.f + expf(-g0)) * acc3[i][n][0];
                h.y = g1 / (1.f + expf(-g1)) * acc3[i][n][1];
                *(float2*)(g_H + (size_t)v0 * FDIM + col) = h;
            }
            if (v1 >= 0) {
                float g2 = acc1[i][n][2], g3 = acc1[i][n][3];
                float2 h;
                h.x = g2 / (1.f + expf(-g2)) * acc3[i][n][2];
                h.y = g3 / (1.f + expf(-g3)) * acc3[i][n][3];
                *(float2*)(g_H + (size_t)v1 * FDIM + col) = h;
            }
        }
    }
}

// ---------------- GEMM2 (tensor core): O = H @ W2 ---------------------------
// BM=128, BN=128, BK=32. 8 warps = 4(m) x 2(n). Warp tile 32x64: 2x8 mma tiles.
__global__ void __launch_bounds__(256) k_gemm2(const float* __restrict__ W2) {
    const int e   = blockIdx.z;
    const int cnt = g_cnt[e];
    const int m0  = blockIdx.x * 128;
    if (m0 >= cnt) return;
    const int n0  = blockIdx.y * 128;

    __shared__ float As[128][36];
    __shared__ float Bs[32][136];     // bank = 8k+n (bijective over warp)
    __shared__ int   sv[128];

    const int tid = threadIdx.x;
    if (tid < 128) {
        int m = m0 + tid;
        sv[tid] = (m < cnt) ? g_list[e][m] : -1;
    }
    __syncthreads();

    const int ar = tid >> 1, ak = (tid & 1) * 16;
    const int svr = sv[ar];
    const float* aptr = g_H + (size_t)(svr < 0 ? 0 : svr) * FDIM + ak;

    const int kr = tid >> 3, nc = (tid & 7) * 16;
    const float* bp = W2 + ((size_t)e * FDIM + kr) * DMODEL + n0 + nc;

    const int wid = tid >> 5, lane = tid & 31;
    const int wm = wid & 3, wn = wid >> 2;
    const int fr = lane >> 2, fc = lane & 3;

    float acc[2][8][4];
    #pragma unroll
    for (int i = 0; i < 2; i++)
        #pragma unroll
        for (int n = 0; n < 8; n++)
            #pragma unroll
            for (int q = 0; q < 4; q++) acc[i][n][q] = 0.f;

    float4 pa[4], pb[4];
    #pragma unroll
    for (int j = 0; j < 4; j++) pa[j] = *(const float4*)(aptr + 4 * j);
    #pragma unroll
    for (int j = 0; j < 4; j++) pb[j] = *(const float4*)(bp + 4 * j);

    const int NK = FDIM / 32;  // 128
    for (int kt = 0; kt < NK; ++kt) {
        #pragma unroll
        for (int j = 0; j < 4; j++) {
            float4 c;
            c.x = tf32r(pa[j].x); c.y = tf32r(pa[j].y);
            c.z = tf32r(pa[j].z); c.w = tf32r(pa[j].w);
            *(float4*)&As[ar][ak + 4 * j] = c;
        }
        #pragma unroll
        for (int j = 0; j < 4; j++) {
            float4 c;
            c.x = tf32r(pb[j].x); c.y = tf32r(pb[j].y);
            c.z = tf32r(pb[j].z); c.w = tf32r(pb[j].w);
            *(float4*)&Bs[kr][nc + 4 * j] = c;
        }
        __syncthreads();
        if (kt + 1 < NK) {
            const int ko = (kt + 1) * 32;
            #pragma unroll
            for (int j = 0; j < 4; j++) pa[j] = *(const float4*)(aptr + ko + 4 * j);
            #pragma unroll
            for (int j = 0; j < 4; j++) pb[j] = *(const float4*)(bp + (size_t)ko * DMODEL + 4 * j);
        }
        #pragma unroll
        for (int s = 0; s < 4; s++) {
            const int kb = s * 8;
            uint32_t a[2][4];
            #pragma unroll
            for (int i = 0; i < 2; i++) {
                const int r = wm * 32 + i * 16 + fr;
                a[i][0] = __float_as_uint(As[r][kb + fc]);
                a[i][1] = __float_as_uint(As[r + 8][kb + fc]);
                a[i][2] = __float_as_uint(As[r][kb + fc + 4]);
                a[i][3] = __float_as_uint(As[r + 8][kb + fc + 4]);
            }
            #pragma unroll
            for (int n = 0; n < 8; n++) {
                const int nb = wn * 64 + n * 8 + fr;
                uint32_t b0 = __float_as_uint(Bs[kb + fc][nb]);
                uint32_t b1 = __float_as_uint(Bs[kb + fc + 4][nb]);
                #pragma unroll
                for (int i = 0; i < 2; i++) {
                    MMA_TF32(acc[i][n], a[i], b0, b1);
                }
            }
        }
        __syncthreads();
    }

    #pragma unroll
    for (int i = 0; i < 2; i++) {
        const int r0 = wm * 32 + i * 16 + fr;
        const int r1 = r0 + 8;
        const int v0 = sv[r0], v1 = sv[r1];
        #pragma unroll
        for (int n = 0; n < 8; n++) {
            const int col = n0 + wn * 64 + n * 8 + fc * 2;
            if (v0 >= 0)
                *(float2*)(g_O + (size_t)v0 * DMODEL + col) =
                    make_float2(acc[i][n][0], acc[i][n][1]);
            if (v1 >= 0)
                *(float2*)(g_O + (size_t)v1 * DMODEL + col) =
                    make_float2(acc[i][n][2], acc[i][n][3]);
        }
    }
}

// ---------------- combine: out[t] = w0*O[2t] + w1*O[2t+1] -------------------
__global__ void k_combine(float* __restrict__ out) {
    const int i  = blockIdx.x * blockDim.x + threadIdx.x;
    const int n4 = TTOK * DMODEL / 4;
    if (i >= n4) return;
    const int t = i / (DMODEL / 4);
    const int c = i % (DMODEL / 4);
    const float w0 = g_wslot[2 * t], w1 = g_wslot[2 * t + 1];
    const float4 o0 = ((const float4*)g_O)[(size_t)(2 * t)     * (DMODEL / 4) + c];
    const float4 o1 = ((const float4*)g_O)[(size_t)(2 * t + 1) * (DMODEL / 4) + c];
    float4 r;
    r.x = w0 * o0.x + w1 * o1.x;
    r.y = w0 * o0.y + w1 * o1.y;
    r.z = w0 * o0.z + w1 * o1.z;
    r.w = w0 * o0.w + w1 * o1.w;
    ((float4*)out)[i] = r;
}

// ---------------- launch -----------------------------------------------------
extern "C" void kernel_launch(void* const* d_in, const int* in_sizes, int n_in,
                              void* d_out, int out_size) {
    const float* x  = (const float*)d_in[0];
    const float* gw = (const float*)d_in[1];
    const float* W1 = (const float*)d_in[2];
    const float* W3 = (const float*)d_in[3];
    const float* W2 = (const float*)d_in[4];
    float* out = (float*)d_out;

    float* logits = ((size_t)out_size >= (size_t)TTOK * DMODEL + (size_t)TTOK * NEXP)
                        ? out + (size_t)TTOK * DMODEL
                        : nullptr;

    k_init<<<1, 32>>>();
    k_router<<<TTOK / 8, 256>>>(x, gw, logits);
    // grid: x = m-blocks (fastest; co-resident CTAs share B panels in L2)
    k_gemm1<<<dim3(TTOK / 128, FDIM / 64, NEXP), 256>>>(x, W1, W3);
    k_gemm2<<<dim3(TTOK / 128, DMODEL / 128, NEXP), 256>>>(W2);
    k_combine<<<(TTOK * DMODEL / 4 + 255) / 256, 256>>>(out);
}

// round 4
// speedup vs baseline: 2.6049x; 1.1548x over previous
#include <cuda_runtime.h>
#include <cstdint>
#include <cstddef>

#define TTOK   8192
#define DMODEL 1024
#define FDIM   4096
#define NEXP   8

#define BK       32
#define ASTRIDE  36          // words per A row (32 + pad) -> bank = 4r + c (bijective)
#define BSTRIDE  264         // words per B k-row (256 + pad) -> bank = 8k + n (bijective)
#define A_WORDS  (128 * ASTRIDE)   // 4608
#define B_WORDS  (BK * BSTRIDE)    // 8448
#define STAGES   3
#define DSMEM_BYTES ((STAGES * (A_WORDS + B_WORDS)) * 4)   // 156672

// ---------------- scratch (static device memory; no allocations) ------------
__device__ int   g_cnt[NEXP];
__device__ int   g_list[NEXP][TTOK];
__device__ float g_wslot[2 * TTOK];
__device__ float g_H[(size_t)2 * TTOK * FDIM];            // 256 MB
__device__ float g_O[(size_t)2 * TTOK * DMODEL];          // 64 MB

__global__ void k_init() {
    if (threadIdx.x < NEXP) g_cnt[threadIdx.x] = 0;
}

// ---------------- helpers ----------------------------------------------------
__device__ __forceinline__ uint32_t tf32u(float f) {
    uint32_t u;
    asm("cvt.rna.tf32.f32 %0, %1;" : "=r"(u) : "f"(f));
    return u;
}
__device__ __forceinline__ uint32_t smem_u32(const void* p) {
    uint32_t a;
    asm("{ .reg .u64 t; cvta.to.shared.u64 t, %1; cvt.u32.u64 %0, t; }"
        : "=r"(a) : "l"(p));
    return a;
}
__device__ __forceinline__ void cp16(uint32_t dst, const float* src, uint32_t srcsize) {
    asm volatile("cp.async.cg.shared.global [%0], [%1], 16, %2;"
                 :: "r"(dst), "l"(src), "r"(srcsize) : "memory");
}
#define CP_COMMIT() asm volatile("cp.async.commit_group;" ::: "memory")
#define CP_WAIT1()  asm volatile("cp.async.wait_group 1;" ::: "memory")

#define MMA_TF32(C, A, B0, B1)                                               \
    asm volatile(                                                            \
        "mma.sync.aligned.m16n8k8.row.col.f32.tf32.tf32.f32 "               \
        "{%0,%1,%2,%3},{%4,%5,%6,%7},{%8,%9},{%0,%1,%2,%3};"                \
        : "+f"((C)[0]), "+f"((C)[1]), "+f"((C)[2]), "+f"((C)[3])            \
        : "r"((A)[0]), "r"((A)[1]), "r"((A)[2]), "r"((A)[3]),               \
          "r"(B0), "r"(B1))

// ---------------- router ------------------------------------------------------
__global__ void __launch_bounds__(256) k_router(const float* __restrict__ x,
                                                const float* __restrict__ gw,
                                                float* logits) {
    __shared__ float sgw[NEXP * DMODEL];
    const int tid = threadIdx.x;
    for (int i = tid; i < NEXP * DMODEL / 4; i += 256)
        ((float4*)sgw)[i] = ((const float4*)gw)[i];
    __syncthreads();

    const int warp = tid >> 5, lane = tid & 31;
    const int t = blockIdx.x * 8 + warp;

    float acc[NEXP];
    #pragma unroll
    for (int e = 0; e < NEXP; e++) acc[e] = 0.f;

    const float4* xv = (const float4*)(x + (size_t)t * DMODEL);
    #pragma unroll
    for (int c = 0; c < DMODEL / 128; c++) {
        float4 xx = xv[c * 32 + lane];
        #pragma unroll
        for (int e = 0; e < NEXP; e++) {
            float4 g = ((const float4*)sgw)[e * (DMODEL / 4) + c * 32 + lane];
            acc[e] += xx.x * g.x + xx.y * g.y + xx.z * g.z + xx.w * g.w;
        }
    }
    #pragma unroll
    for (int off = 16; off > 0; off >>= 1) {
        #pragma unroll
        for (int e = 0; e < NEXP; e++)
            acc[e] += __shfl_xor_sync(0xffffffffu, acc[e], off);
    }

    if (lane == 0) {
        if (logits) {
            #pragma unroll
            for (int e = 0; e < NEXP; e++) logits[(size_t)t * NEXP + e] = acc[e];
        }
        int e0 = 0;
        #pragma unroll
        for (int e = 1; e < NEXP; e++) if (acc[e] > acc[e0]) e0 = e;
        int e1 = -1;
        #pragma unroll
        for (int e = 0; e < NEXP; e++) {
            if (e == e0) continue;
            if (e1 < 0 || acc[e] > acc[e1]) e1 = e;
        }
        float w0 = 1.f / (1.f + expf(acc[e1] - acc[e0]));
        float w1 = 1.f - w0;
        int s0 = atomicAdd(&g_cnt[e0], 1);
        g_list[e0][s0] = t * 2;
        int s1 = atomicAdd(&g_cnt[e1], 1);
        g_list[e1][s1] = t * 2 + 1;
        g_wslot[2 * t]     = w0;
        g_wslot[2 * t + 1] = w1;
    }
}

// ---------------- GEMM1: H = silu(x@W1) * (x@W3) -----------------------------
// CTA: 128 m x (128 W1-cols + 128 W3-cols), BK=32, 8 warps (2m x 4n),
// warp: 64 m x (32 W1 + 32 W3). 3-stage cp.async pipeline.
__global__ void __launch_bounds__(256) k_gemm1(const float* __restrict__ x,
                                               const float* __restrict__ W1,
                                               const float* __restrict__ W3) {
    const int e   = blockIdx.z;
    const int cnt = g_cnt[e];
    const int m0  = blockIdx.x * 128;
    if (m0 >= cnt) return;
    const int n0  = blockIdx.y * 128;

    extern __shared__ float ds[];
    __shared__ int sv[128];

    const int tid = threadIdx.x;
    if (tid < 128) sv[tid] = (m0 + tid < cnt) ? g_list[e][m0 + tid] : -1;
    __syncthreads();

    const uint32_t sbase = smem_u32(ds);

    // ---- staging descriptors ----
    // A: 4 chunks/thread: row r_t = (tid>>3)+32t, kc = (tid&7)*4
    const int akc = (tid & 7) * 4;
    const float* asrc[4];
    uint32_t adst[4], asz[4];
    #pragma unroll
    for (int t = 0; t < 4; t++) {
        const int r = (tid >> 3) + 32 * t;
        const int slot = sv[r];
        asrc[t] = x + (size_t)((slot < 0 ? 0 : slot) >> 1) * DMODEL + akc;
        asz[t]  = (slot >= 0) ? 16u : 0u;
        adst[t] = sbase + (uint32_t)(r * ASTRIDE + akc) * 4u;
    }
    // B: 8 chunks/thread: k = (tid>>6)+4t; j = tid&63 (j<32 -> W1, else W3)
    const int bj = tid & 63;
    const int bk0 = tid >> 6;
    const float* bsrc = ((bj < 32) ? W1 : W3) + (size_t)e * DMODEL * FDIM
                        + n0 + (bj & 31) * 4;
    const uint32_t bdst = sbase + (uint32_t)(STAGES * A_WORDS) * 4u
                        + (uint32_t)(bk0 * BSTRIDE + ((bj < 32) ? 0 : 128) + (bj & 31) * 4) * 4u;

    #define G1_STAGE(s, k0) do {                                              \
        const uint32_t _ao = (uint32_t)(s) * A_WORDS * 4u;                    \
        _Pragma("unroll")                                                     \
        for (int t = 0; t < 4; t++) cp16(adst[t] + _ao, asrc[t] + (k0), asz[t]); \
        const uint32_t _bo = (uint32_t)(s) * B_WORDS * 4u;                    \
        _Pragma("unroll")                                                     \
        for (int t = 0; t < 8; t++)                                           \
            cp16(bdst + _bo + (uint32_t)t * 4u * BSTRIDE * 4u,                \
                 bsrc + (size_t)((k0) + bk0 + 4 * t) * FDIM, 16u);            \
        CP_COMMIT();                                                          \
    } while (0)

    const int wid = tid >> 5, lane = tid & 31;
    const int wm = wid & 1, wn = wid >> 1;
    const int fr = lane >> 2, fc = lane & 3;

    float acc1[4][4][4], acc3[4][4][4];
    #pragma unroll
    for (int i = 0; i < 4; i++)
        #pragma unroll
        for (int n = 0; n < 4; n++)
            #pragma unroll
            for (int q = 0; q < 4; q++) { acc1[i][n][q] = 0.f; acc3[i][n][q] = 0.f; }

    const int NK = DMODEL / BK;   // 32
    G1_STAGE(0, 0);
    G1_STAGE(1, BK);

    for (int kt = 0; kt < NK; ++kt) {
        CP_WAIT1();
        __syncthreads();
        if (kt + 2 < NK) { G1_STAGE((kt + 2) % 3, (kt + 2) * BK); }
        else CP_COMMIT();

        const float* A_ = ds + (kt % 3) * A_WORDS;
        const float* B_ = ds + STAGES * A_WORDS + (kt % 3) * B_WORDS;

        #pragma unroll
        for (int s = 0; s < 4; s++) {
            const int kb = s * 8;
            uint32_t a[4][4];
            #pragma unroll
            for (int i = 0; i < 4; i++) {
                const int r = wm * 64 + i * 16 + fr;
                a[i][0] = tf32u(A_[r * ASTRIDE + kb + fc]);
                a[i][1] = tf32u(A_[(r + 8) * ASTRIDE + kb + fc]);
                a[i][2] = tf32u(A_[r * ASTRIDE + kb + fc + 4]);
                a[i][3] = tf32u(A_[(r + 8) * ASTRIDE + kb + fc + 4]);
            }
            #pragma unroll
            for (int nt = 0; nt < 4; nt++) {
                const int col = wn * 32 + nt * 8 + fr;
                uint32_t b10 = tf32u(B_[(kb + fc) * BSTRIDE + col]);
                uint32_t b11 = tf32u(B_[(kb + fc + 4) * BSTRIDE + col]);
                uint32_t b30 = tf32u(B_[(kb + fc) * BSTRIDE + 128 + col]);
                uint32_t b31 = tf32u(B_[(kb + fc + 4) * BSTRIDE + 128 + col]);
                #pragma unroll
                for (int i = 0; i < 4; i++) {
                    MMA_TF32(acc1[i][nt], a[i], b10, b11);
                    MMA_TF32(acc3[i][nt], a[i], b30, b31);
                }
            }
        }
        __syncthreads();
    }

    // epilogue: silu(acc1)*acc3 -> g_H
    #pragma unroll
    for (int i = 0; i < 4; i++) {
        const int r0 = wm * 64 + i * 16 + fr;
        const int v0 = sv[r0], v1 = sv[r0 + 8];
        #pragma unroll
        for (int nt = 0; nt < 4; nt++) {
            const int col = n0 + wn * 32 + nt * 8 + fc * 2;
            if (v0 >= 0) {
                float g0 = acc1[i][nt][0], g1 = acc1[i][nt][1];
                float2 h;
                h.x = g0 / (1.f + expf(-g0)) * acc3[i][nt][0];
                h.y = g1 / (1.f + expf(-g1)) * acc3[i][nt][1];
                *(float2*)(g_H + (size_t)v0 * FDIM + col) = h;
            }
            if (v1 >= 0) {
                float g2 = acc1[i][nt][2], g3 = acc1[i][nt][3];
                float2 h;
                h.x = g2 / (1.f + expf(-g2)) * acc3[i][nt][2];
                h.y = g3 / (1.f + expf(-g3)) * acc3[i][nt][3];
                *(float2*)(g_H + (size_t)v1 * FDIM + col) = h;
            }
        }
    }
    #undef G1_STAGE
}

// ---------------- GEMM2: O = H @ W2 -------------------------------------------
// CTA: 128 m x 256 n, BK=32, 8 warps (2m x 4n), warp 64x64.
__global__ void __launch_bounds__(256) k_gemm2(const float* __restrict__ W2) {
    const int e   = blockIdx.z;
    const int cnt = g_cnt[e];
    const int m0  = blockIdx.x * 128;
    if (m0 >= cnt) return;
    const int n0  = blockIdx.y * 256;

    extern __shared__ float ds[];
    __shared__ int sv[128];

    const int tid = threadIdx.x;
    if (tid < 128) sv[tid] = (m0 + tid < cnt) ? g_list[e][m0 + tid] : -1;
    __syncthreads();

    const uint32_t sbase = smem_u32(ds);

    const int akc = (tid & 7) * 4;
    const float* asrc[4];
    uint32_t adst[4], asz[4];
    #pragma unroll
    for (int t = 0; t < 4; t++) {
        const int r = (tid >> 3) + 32 * t;
        const int slot = sv[r];
        asrc[t] = g_H + (size_t)(slot < 0 ? 0 : slot) * FDIM + akc;
        asz[t]  = (slot >= 0) ? 16u : 0u;
        adst[t] = sbase + (uint32_t)(r * ASTRIDE + akc) * 4u;
    }
    const int bnc = (tid & 63) * 4;
    const int bk0 = tid >> 6;
    const float* bsrc = W2 + (size_t)e * FDIM * DMODEL + n0 + bnc;
    const uint32_t bdst = sbase + (uint32_t)(STAGES * A_WORDS) * 4u
                        + (uint32_t)(bk0 * BSTRIDE + bnc) * 4u;

    #define G2_STAGE(s, k0) do {                                              \
        const uint32_t _ao = (uint32_t)(s) * A_WORDS * 4u;                    \
        _Pragma("unroll")                                                     \
        for (int t = 0; t < 4; t++) cp16(adst[t] + _ao, asrc[t] + (k0), asz[t]); \
        const uint32_t _bo = (uint32_t)(s) * B_WORDS * 4u;                    \
        _Pragma("unroll")                                                     \
        for (int t = 0; t < 8; t++)                                           \
            cp16(bdst + _bo + (uint32_t)t * 4u * BSTRIDE * 4u,                \
                 bsrc + (size_t)((k0) + bk0 + 4 * t) * DMODEL, 16u);          \
        CP_COMMIT();                                                          \
    } while (0)

    const int wid = tid >> 5, lane = tid & 31;
    const int wm = wid & 1, wn = wid >> 1;
    const int fr = lane >> 2, fc = lane & 3;

    float acc[4][8][4];
    #pragma unroll
    for (int i = 0; i < 4; i++)
        #pragma unroll
        for (int n = 0; n < 8; n++)
            #pragma unroll
            for (int q = 0; q < 4; q++) acc[i][n][q] = 0.f;

    const int NK = FDIM / BK;   // 128
    G2_STAGE(0, 0);
    G2_STAGE(1, BK);

    for (int kt = 0; kt < NK; ++kt) {
        CP_WAIT1();
        __syncthreads();
        if (kt + 2 < NK) { G2_STAGE((kt + 2) % 3, (kt + 2) * BK); }
        else CP_COMMIT();

        const float* A_ = ds + (kt % 3) * A_WORDS;
        const float* B_ = ds + STAGES * A_WORDS + (kt % 3) * B_WORDS;

        #pragma unroll
        for (int s = 0; s < 4; s++) {
            const int kb = s * 8;
            uint32_t a[4][4];
            #pragma unroll
            for (int i = 0; i < 4; i++) {
                const int r = wm * 64 + i * 16 + fr;
                a[i][0] = tf32u(A_[r * ASTRIDE + kb + fc]);
                a[i][1] = tf32u(A_[(r + 8) * ASTRIDE + kb + fc]);
                a[i][2] = tf32u(A_[r * ASTRIDE + kb + fc + 4]);
                a[i][3] = tf32u(A_[(r + 8) * ASTRIDE + kb + fc + 4]);
            }
            #pragma unroll
            for (int nt = 0; nt < 8; nt++) {
                const int col = wn * 64 + nt * 8 + fr;
                uint32_t b0 = tf32u(B_[(kb + fc) * BSTRIDE + col]);
                uint32_t b1 = tf32u(B_[(kb + fc + 4) * BSTRIDE + col]);
                #pragma unroll
                for (int i = 0; i < 4; i++)
                    MMA_TF32(acc[i][nt], a[i], b0, b1);
            }
        }
        __syncthreads();
    }

    #pragma unroll
    for (int i = 0; i < 4; i++) {
        const int r0 = wm * 64 + i * 16 + fr;
        const int v0 = sv[r0], v1 = sv[r0 + 8];
        #pragma unroll
        for (int nt = 0; nt < 8; nt++) {
            const int col = n0 + wn * 64 + nt * 8 + fc * 2;
            if (v0 >= 0)
                *(float2*)(g_O + (size_t)v0 * DMODEL + col) =
                    make_float2(acc[i][nt][0], acc[i][nt][1]);
            if (v1 >= 0)
                *(float2*)(g_O + (size_t)v1 * DMODEL + col) =
                    make_float2(acc[i][nt][2], acc[i][nt][3]);
        }
    }
    #undef G2_STAGE
}

// ---------------- combine ------------------------------------------------------
__global__ void k_combine(float* __restrict__ out) {
    const int i  = blockIdx.x * blockDim.x + threadIdx.x;
    const int n4 = TTOK * DMODEL / 4;
    if (i >= n4) return;
    const int t = i / (DMODEL / 4);
    const int c = i % (DMODEL / 4);
    const float w0 = g_wslot[2 * t], w1 = g_wslot[2 * t + 1];
    const float4 o0 = ((const float4*)g_O)[(size_t)(2 * t)     * (DMODEL / 4) + c];
    const float4 o1 = ((const float4*)g_O)[(size_t)(2 * t + 1) * (DMODEL / 4) + c];
    float4 r;
    r.x = w0 * o0.x + w1 * o1.x;
    r.y = w0 * o0.y + w1 * o1.y;
    r.z = w0 * o0.z + w1 * o1.z;
    r.w = w0 * o0.w + w1 * o1.w;
    ((float4*)out)[i] = r;
}

// ---------------- launch --------------------------------------------------------
extern "C" void kernel_launch(void* const* d_in, const int* in_sizes, int n_in,
                              void* d_out, int out_size) {
    const float* x  = (const float*)d_in[0];
    const float* gw = (const float*)d_in[1];
    const float* W1 = (const float*)d_in[2];
    const float* W3 = (const float*)d_in[3];
    const float* W2 = (const float*)d_in[4];
    float* out = (float*)d_out;

    float* logits = ((size_t)out_size >= (size_t)TTOK * DMODEL + (size_t)TTOK * NEXP)
                        ? out + (size_t)TTOK * DMODEL
                        : nullptr;

    static int smem_set = 0;
    if (!smem_set) {
        cudaFuncSetAttribute(k_gemm1, cudaFuncAttributeMaxDynamicSharedMemorySize, DSMEM_BYTES);
        cudaFuncSetAttribute(k_gemm2, cudaFuncAttributeMaxDynamicSharedMemorySize, DSMEM_BYTES);
        smem_set = 1;
    }

    k_init<<<1, 32>>>();
    k_router<<<TTOK / 8, 256>>>(x, gw, logits);
    // m-blocks fastest: co-resident CTAs share the same B panel through L2.
    k_gemm1<<<dim3(TTOK / 128, FDIM / 128, NEXP), 256, DSMEM_BYTES>>>(x, W1, W3);
    k_gemm2<<<dim3(TTOK / 128, DMODEL / 256, NEXP), 256, DSMEM_BYTES>>>(W2);
    k_combine<<<(TTOK * DMODEL / 4 + 255) / 256, 256>>>(out);
}